// round 15
// baseline (speedup 1.0000x reference)
#include <cuda_runtime.h>
#include <cuda_bf16.h>
#include <math.h>
#include <stdint.h>

#define BATCH  4
#define SLEN   2048
#define DMODEL 1024
#define NHEAD  16
#define DHEAD  64
// K is pre-scaled by ATT_SCALE * log2(e): softmax runs in exp2 domain.
#define K_SCALE 0.1803368801111204f   // 0.125 * 1.4426950408889634

// ---------------------------------------------------------------------------
// Device scratch (no cudaMalloc allowed). All projected tensors stored as
// pre-split bf16 hi/lo pairs; K pre-scaled. W^T pre-split too.
// ---------------------------------------------------------------------------
#define NTOK (BATCH * SLEN * DMODEL)
__device__ __nv_bfloat16 g_qh[NTOK], g_ql[NTOK];
__device__ __nv_bfloat16 g_kh[NTOK], g_kl[NTOK];
__device__ __nv_bfloat16 g_vh[NTOK], g_vl[NTOK];
__device__ __nv_bfloat16 g_wth[3 * DMODEL * DMODEL], g_wtl[3 * DMODEL * DMODEL];
__device__ int g_idx[BATCH * SLEN];
__device__ int g_nv[BATCH];

// ---------------------------------------------------------------------------
// Helpers
// ---------------------------------------------------------------------------
__device__ __forceinline__ void mma16(float c[4], const uint32_t a[4],
                                      const uint32_t b[2]) {
    asm volatile(
        "mma.sync.aligned.m16n8k16.row.col.f32.bf16.bf16.f32 "
        "{%0,%1,%2,%3}, {%4,%5,%6,%7}, {%8,%9}, {%0,%1,%2,%3};"
        : "+f"(c[0]), "+f"(c[1]), "+f"(c[2]), "+f"(c[3])
        : "r"(a[0]), "r"(a[1]), "r"(a[2]), "r"(a[3]),
          "r"(b[0]), "r"(b[1]));
}

__device__ __forceinline__ void ldsm4(uint32_t r[4], uint32_t addr) {
    asm volatile(
        "ldmatrix.sync.aligned.m8n8.x4.shared.b16 {%0,%1,%2,%3}, [%4];"
        : "=r"(r[0]), "=r"(r[1]), "=r"(r[2]), "=r"(r[3]) : "r"(addr));
}

__device__ __forceinline__ void ldsm4t(uint32_t r[4], uint32_t addr) {
    asm volatile(
        "ldmatrix.sync.aligned.m8n8.x4.trans.shared.b16 {%0,%1,%2,%3}, [%4];"
        : "=r"(r[0]), "=r"(r[1]), "=r"(r[2]), "=r"(r[3]) : "r"(addr));
}

__device__ __forceinline__ uint32_t sptr(const void* p) {
    return (uint32_t)__cvta_generic_to_shared(p);
}

__device__ __forceinline__ void cpa16(uint32_t s, const void* g) {
    asm volatile("cp.async.cg.shared.global [%0], [%1], 16;" :: "r"(s), "l"(g));
}
#define CP_COMMIT() asm volatile("cp.async.commit_group;" ::: "memory")
#define CP_WAIT(n)  asm volatile("cp.async.wait_group %0;" :: "n"(n) : "memory")

__device__ __forceinline__ float ex2(float x) {
    float r;
    asm("ex2.approx.f32 %0, %1;" : "=f"(r) : "f"(x));
    return r;
}

__device__ __forceinline__ void split2(float x0, float x1, uint32_t& h,
                                       uint32_t& l) {
    __nv_bfloat162 hb = __floats2bfloat162_rn(x0, x1);
    const float2 hf = __bfloat1622float2(hb);
    __nv_bfloat162 lb = __floats2bfloat162_rn(x0 - hf.x, x1 - hf.y);
    h = *reinterpret_cast<uint32_t*>(&hb);
    l = *reinterpret_cast<uint32_t*>(&lb);
}

// ---------------------------------------------------------------------------
// Mask compaction: per batch, prefix-scan the key-padding mask.
// ---------------------------------------------------------------------------
__global__ __launch_bounds__(256)
void compact_mask(const int* __restrict__ mask)
{
    __shared__ int part[256];
    const int b   = blockIdx.x;
    const int tid = threadIdx.x;
    const int* mb = mask + b * SLEN;

    int loc[8];
    int cnt = 0;
#pragma unroll
    for (int e = 0; e < 8; e++) {
        loc[e] = cnt;
        cnt += (mb[tid * 8 + e] != 0);
    }
    part[tid] = cnt;
    __syncthreads();
#pragma unroll
    for (int off = 1; off < 256; off <<= 1) {
        const int v = (tid >= off) ? part[tid - off] : 0;
        __syncthreads();
        part[tid] += v;
        __syncthreads();
    }
    const int excl = part[tid] - cnt;
#pragma unroll
    for (int e = 0; e < 8; e++) {
        if (mb[tid * 8 + e] != 0)
            g_idx[b * SLEN + excl + loc[e]] = tid * 8 + e;
    }
    const int total = part[255];
    if (tid == 0) g_nv[b] = total;
    __syncthreads();
    for (int j = total + tid; j < SLEN; j += 256)
        g_idx[b * SLEN + j] = 0;
}

// ---------------------------------------------------------------------------
// W^T prep: transpose + bf16 hi/lo split all three weight matrices.
// ---------------------------------------------------------------------------
__global__ __launch_bounds__(256)
void wT_split(const float* __restrict__ W0, const float* __restrict__ W1,
              const float* __restrict__ W2)
{
    __shared__ float t[32][33];
    const int z  = blockIdx.z;
    const float* W = (z == 0) ? W0 : (z == 1) ? W1 : W2;
    const int x  = blockIdx.x * 32 + threadIdx.x;
    const int y0 = blockIdx.y * 32;
#pragma unroll
    for (int i = threadIdx.y; i < 32; i += 8)
        t[i][threadIdx.x] = W[(size_t)(y0 + i) * DMODEL + x];
    __syncthreads();
    const int ko = y0 + threadIdx.x;
    const int no = blockIdx.x * 32;
    __nv_bfloat16* th = g_wth + (size_t)z * DMODEL * DMODEL;
    __nv_bfloat16* tl = g_wtl + (size_t)z * DMODEL * DMODEL;
#pragma unroll
    for (int i = threadIdx.y; i < 32; i += 8) {
        const float v = t[threadIdx.x][i];
        const __nv_bfloat16 h = __float2bfloat16(v);
        th[(size_t)(no + i) * DMODEL + ko] = h;
        tl[(size_t)(no + i) * DMODEL + ko] =
            __float2bfloat16(v - __bfloat162float(h));
    }
}

// ---------------------------------------------------------------------------
// Fused projection GEMMs, BK=64, 16 phases (R12 structure; B cp.async issued
// FIRST so its latency drains under the A-tile split work).
// z=0: Q. z=1: K (pre-scaled by K_SCALE). z=2: V (gathered via g_idx).
// ---------------------------------------------------------------------------
#define PSTR 36
#define PROJ_SMEM (4 * 128 * PSTR * 4)   // 73728 bytes

__global__ __launch_bounds__(256, 2)
void proj_mma(const float* __restrict__ X0, const float* __restrict__ X1,
              const float* __restrict__ X2,
              const float* __restrict__ b0, const float* __restrict__ b1,
              const float* __restrict__ b2)
{
    extern __shared__ uint32_t smw[];
    uint32_t* Ah = smw;                    // [128][PSTR]
    uint32_t* Al = Ah + 128 * PSTR;
    uint32_t* Bh = Al + 128 * PSTR;
    uint32_t* Bl = Bh + 128 * PSTR;

    const int z = blockIdx.z;
    const float* X    = (z == 0) ? X0 : (z == 1) ? X1 : X2;
    const float* bias = (z == 0) ? b0 : (z == 1) ? b1 : b2;
    __nv_bfloat16* Yh = (z == 0) ? g_qh : (z == 1) ? g_kh : g_vh;
    __nv_bfloat16* Yl = (z == 0) ? g_ql : (z == 1) ? g_kl : g_vl;
    const __nv_bfloat16* WTh = g_wth + (size_t)z * DMODEL * DMODEL;
    const __nv_bfloat16* WTl = g_wtl + (size_t)z * DMODEL * DMODEL;
    const float oscale = (z == 1) ? K_SCALE : 1.0f;

    const int m0   = blockIdx.y * 128;
    const int n0   = blockIdx.x * 128;
    const int bb   = m0 >> 11;
    const int mloc = m0 & 2047;

    const int nvb = (z == 0) ? SLEN : g_nv[bb];
    if (mloc >= nvb) return;
    const int* idxb = g_idx + bb * SLEN;

    const int tid  = threadIdx.x;
    const int lane = tid & 31;
    const int w    = tid >> 5;
    const int g    = lane >> 2;
    const int tig  = lane & 3;
    const int wm   = (w >> 2) * 64;
    const int wn   = (w & 3) * 32;

    const int lane15  = lane & 15;
    const int halfsel = (lane >> 4) & 1;
    const int krow    = (lane & 7) + ((lane & 16) >> 1);
    const int kcol    = (lane & 8) >> 1;

    const uint32_t pa = sptr(Ah) + ((wm + lane15) * PSTR + halfsel * 4) * 4;
    const uint32_t pb = sptr(Bh) + ((wn + krow) * PSTR + kcol) * 4;
    const uint32_t ALO = 128 * PSTR * 4;
    const uint32_t BLO = 128 * PSTR * 4;

    // source row for each of this thread's 8 A-tile rows (gathered for K/V)
    int srow[8];
#pragma unroll
    for (int it = 0; it < 8; it++) {
        const int r = (tid + it * 256) >> 4;
        if (z == 0) srow[it] = m0 + r;
        else {
            const int j = mloc + r;
            srow[it] = (bb << 11) + ((j < nvb) ? idxb[j] : idxb[0]);
        }
    }

    const uint32_t sBh = sptr(Bh), sBl = sptr(Bl);

    float acc[4][4][4];
#pragma unroll
    for (int i = 0; i < 4; i++)
#pragma unroll
        for (int j = 0; j < 4; j++)
#pragma unroll
            for (int r = 0; r < 4; r++) acc[i][j][r] = 0.f;

    for (int k0 = 0; k0 < DMODEL; k0 += 64) {
        // ---- B tile FIRST: cp.async issue, latency drains under A work
#pragma unroll
        for (int it = 0; it < 4; it++) {
            const int idx = tid + it * 256;
            const int n = idx >> 3, ch = idx & 7;
            const size_t gg = (size_t)(n0 + n) * DMODEL + k0 + ch * 8;
            const uint32_t sm = (n * PSTR + ch * 4) * 4;
            cpa16(sBh + sm, WTh + gg);
            cpa16(sBl + sm, WTl + gg);
        }
        CP_COMMIT();

        // ---- A tile: fp32 X rows (64 k), split to bf16 hi/lo
#pragma unroll
        for (int it = 0; it < 8; it++) {
            const int idx = tid + it * 256;
            const int r = idx >> 4, c = (idx & 15) << 2;
            const float4 v = *(const float4*)(X + (size_t)srow[it] * DMODEL + k0 + c);
            uint32_t h0, l0, h1, l1;
            split2(v.x, v.y, h0, l0);
            split2(v.z, v.w, h1, l1);
            *(uint2*)&Ah[r * PSTR + (c >> 1)] = make_uint2(h0, h1);
            *(uint2*)&Al[r * PSTR + (c >> 1)] = make_uint2(l0, l1);
        }
        CP_WAIT(0);
        __syncthreads();

#pragma unroll
        for (int ks = 0; ks < 4; ks++) {
            uint32_t bh0[4], bl0[4], bh1[4], bl1[4];
            ldsm4(bh0, pb + ks * 32);
            ldsm4(bl0, pb + ks * 32 + BLO);
            ldsm4(bh1, pb + 16 * PSTR * 4 + ks * 32);
            ldsm4(bl1, pb + 16 * PSTR * 4 + ks * 32 + BLO);
#pragma unroll
            for (int i = 0; i < 4; i++) {
                uint32_t ah[4], al[4];
                ldsm4(ah, pa + i * 16 * PSTR * 4 + ks * 32);
                ldsm4(al, pa + i * 16 * PSTR * 4 + ks * 32 + ALO);
                mma16(acc[i][0], ah, bh0);     mma16(acc[i][0], ah, bl0);
                mma16(acc[i][0], al, bh0);
                mma16(acc[i][1], ah, bh0 + 2); mma16(acc[i][1], ah, bl0 + 2);
                mma16(acc[i][1], al, bh0 + 2);
                mma16(acc[i][2], ah, bh1);     mma16(acc[i][2], ah, bl1);
                mma16(acc[i][2], al, bh1);
                mma16(acc[i][3], ah, bh1 + 2); mma16(acc[i][3], ah, bl1 + 2);
                mma16(acc[i][3], al, bh1 + 2);
            }
        }
        __syncthreads();
    }

    // ---- epilogue: (+bias) * oscale, split to bf16 hi/lo, store
#pragma unroll
    for (int j = 0; j < 4; j++) {
        const int col = n0 + wn + j * 8 + 2 * tig;
        const float bx = bias[col], by = bias[col + 1];
#pragma unroll
        for (int i = 0; i < 4; i++) {
            const int r0 = m0 + wm + i * 16 + g;
            uint32_t h0, l0, h1, l1;
            split2((acc[i][j][0] + bx) * oscale, (acc[i][j][1] + by) * oscale,
                   h0, l0);
            split2((acc[i][j][2] + bx) * oscale, (acc[i][j][3] + by) * oscale,
                   h1, l1);
            *(uint32_t*)&Yh[(size_t)r0 * DMODEL + col]       = h0;
            *(uint32_t*)&Yl[(size_t)r0 * DMODEL + col]       = l0;
            *(uint32_t*)&Yh[(size_t)(r0 + 8) * DMODEL + col] = h1;
            *(uint32_t*)&Yl[(size_t)(r0 + 8) * DMODEL + col] = l1;
        }
    }
}

// ---------------------------------------------------------------------------
// Flash attention over PACKED pre-split bf16 keys, double-buffered K/V.
// Scores arrive in log2 domain (K pre-scaled by 0.125*log2e) -> bare ex2.
// ---------------------------------------------------------------------------
#define ASTR   36
#define KVW    (4 * 64 * ASTR)
#define ATTN_SMEM ((2 * 128 * ASTR + 2 * KVW) * 4)   // 110592 bytes

__global__ __launch_bounds__(256, 2)
void attn_mma(float* __restrict__ out)
{
    extern __shared__ uint32_t smw[];
    const int tid  = threadIdx.x;
    const int lane = tid & 31;
    const int w    = tid >> 5;
    const int tig  = lane & 3;
    const int wm   = w * 16;
    const int q0   = blockIdx.x << 7;
    const int h    = blockIdx.y;
    const int b    = blockIdx.z;

    const size_t base = (size_t)b * SLEN * DMODEL + h * DHEAD;
    const __nv_bfloat16* qhg = g_qh + base;
    const __nv_bfloat16* qlg = g_ql + base;
    const __nv_bfloat16* khg = g_kh + base;
    const __nv_bfloat16* klg = g_kl + base;
    const __nv_bfloat16* vhg = g_vh + base;
    const __nv_bfloat16* vlg = g_vl + base;
    const int nvb   = g_nv[b];
    const int ntile = (nvb + 63) >> 6;

    const int lane15  = lane & 15;
    const int halfsel = (lane >> 4) & 1;
    const int krow    = (lane & 7) + ((lane & 16) >> 1);
    const int kcol    = (lane & 8) >> 1;

    const uint32_t sbase  = sptr(smw);
    const uint32_t kvbase = sbase + 9216u * 4;
    const uint32_t qa  = sbase + ((wm + lane15) * ASTR + halfsel * 4) * 4;
    const uint32_t QLO = 4608u * 4;
    const uint32_t kaB = (krow * ASTR + kcol) * 4;
    const uint32_t vaB = 4608u * 4 + (lane15 * ASTR + halfsel * 4) * 4;
    const uint32_t LO  = 2304u * 4;

    // ---- Q fill (cp.async)
#pragma unroll
    for (int it = 0; it < 4; it++) {
        const int idx = tid + it * 256;
        const int r = idx >> 3, ch = idx & 7;
        const size_t gg = (size_t)(q0 + r) * DMODEL + ch * 8;
        const uint32_t sm = (r * ASTR + ch * 4) * 4;
        cpa16(sbase + sm, qhg + gg);
        cpa16(sbase + QLO + sm, qlg + gg);
    }
    CP_COMMIT();

    // ---- K/V prefetch tile 0
#pragma unroll
    for (int it = 0; it < 2; it++) {
        const int idx = tid + it * 256;
        const int r = idx >> 3, ch = idx & 7;
        const size_t gg = (size_t)r * DMODEL + ch * 8;
        const uint32_t sm = (r * ASTR + ch * 4) * 4;
        cpa16(kvbase + sm,          khg + gg);
        cpa16(kvbase + LO + sm,     klg + gg);
        cpa16(kvbase + 2 * LO + sm, vhg + gg);
        cpa16(kvbase + 3 * LO + sm, vlg + gg);
    }
    CP_COMMIT();

    float O[8][4];
#pragma unroll
    for (int j = 0; j < 8; j++)
#pragma unroll
        for (int r = 0; r < 4; r++) O[j][r] = 0.f;
    float mrow0 = -1e30f, mrow1 = -1e30f, lrow0 = 0.f, lrow1 = 0.f;

    const unsigned FULL = 0xffffffffu;

    for (int t = 0; t < ntile; t++) {
        if (t + 1 < ntile) {
            const int k1 = (t + 1) << 6;
            const uint32_t st = kvbase + (uint32_t)((t + 1) & 1) * (KVW * 4);
#pragma unroll
            for (int it = 0; it < 2; it++) {
                const int idx = tid + it * 256;
                const int r = idx >> 3, ch = idx & 7;
                const size_t gg = (size_t)(k1 + r) * DMODEL + ch * 8;
                const uint32_t sm = (r * ASTR + ch * 4) * 4;
                cpa16(st + sm,          khg + gg);
                cpa16(st + LO + sm,     klg + gg);
                cpa16(st + 2 * LO + sm, vhg + gg);
                cpa16(st + 3 * LO + sm, vlg + gg);
            }
            CP_COMMIT();
            CP_WAIT(1);
        } else {
            CP_WAIT(0);
        }
        __syncthreads();

        const int k0 = t << 6;
        const uint32_t kvb = kvbase + (uint32_t)(t & 1) * (KVW * 4);
        const uint32_t ka = kvb + kaB;
        const uint32_t va = kvb + vaB;

        // ---- S = Q @ K^T (bf16x3; K pre-scaled into log2 domain)
        float S[8][4];
#pragma unroll
        for (int j = 0; j < 8; j++)
#pragma unroll
            for (int r = 0; r < 4; r++) S[j][r] = 0.f;

#pragma unroll
        for (int ks = 0; ks < 4; ks++) {
            uint32_t ah[4], al[4];
            ldsm4(ah, qa + ks * 32);
            ldsm4(al, qa + ks * 32 + QLO);
#pragma unroll
            for (int jp = 0; jp < 4; jp++) {
                uint32_t bh[4], bl[4];
                const uint32_t kaddr = ka + jp * 16 * ASTR * 4 + ks * 32;
                ldsm4(bh, kaddr);
                ldsm4(bl, kaddr + LO);
                mma16(S[2 * jp], ah, bh);         mma16(S[2 * jp], ah, bl);
                mma16(S[2 * jp], al, bh);
                mma16(S[2 * jp + 1], ah, bh + 2); mma16(S[2 * jp + 1], ah, bl + 2);
                mma16(S[2 * jp + 1], al, bh + 2);
            }
        }

        // ---- tail mask only on the final partial tile
        float mx0 = -1e30f, mx1 = -1e30f;
        if (k0 + 64 > nvb) {
#pragma unroll
            for (int j = 0; j < 8; j++) {
                const int c = k0 + j * 8 + 2 * tig;
                if (c >= nvb)     { S[j][0] = -1e9f; S[j][2] = -1e9f; }
                if (c + 1 >= nvb) { S[j][1] = -1e9f; S[j][3] = -1e9f; }
            }
        }
#pragma unroll
        for (int j = 0; j < 8; j++) {
            mx0 = fmaxf(mx0, fmaxf(S[j][0], S[j][1]));
            mx1 = fmaxf(mx1, fmaxf(S[j][2], S[j][3]));
        }
        mx0 = fmaxf(mx0, __shfl_xor_sync(FULL, mx0, 1));
        mx0 = fmaxf(mx0, __shfl_xor_sync(FULL, mx0, 2));
        mx1 = fmaxf(mx1, __shfl_xor_sync(FULL, mx1, 1));
        mx1 = fmaxf(mx1, __shfl_xor_sync(FULL, mx1, 2));

        const float mnew0 = fmaxf(mrow0, mx0);
        const float mnew1 = fmaxf(mrow1, mx1);
        const float fac0  = ex2(mrow0 - mnew0);
        const float fac1  = ex2(mrow1 - mnew1);

        float sum0 = 0.f, sum1 = 0.f;
#pragma unroll
        for (int j = 0; j < 8; j++) {
            S[j][0] = ex2(S[j][0] - mnew0);
            S[j][1] = ex2(S[j][1] - mnew0);
            S[j][2] = ex2(S[j][2] - mnew1);
            S[j][3] = ex2(S[j][3] - mnew1);
            sum0 += S[j][0] + S[j][1];
            sum1 += S[j][2] + S[j][3];
        }
        sum0 += __shfl_xor_sync(FULL, sum0, 1);
        sum0 += __shfl_xor_sync(FULL, sum0, 2);
        sum1 += __shfl_xor_sync(FULL, sum1, 1);
        sum1 += __shfl_xor_sync(FULL, sum1, 2);

        lrow0 = lrow0 * fac0 + sum0;
        lrow1 = lrow1 * fac1 + sum1;
        mrow0 = mnew0;
        mrow1 = mnew1;

#pragma unroll
        for (int j = 0; j < 8; j++) {
            O[j][0] *= fac0; O[j][1] *= fac0;
            O[j][2] *= fac1; O[j][3] *= fac1;
        }

        // ---- O += P @ V (P in-register cvt; V via ldmatrix.trans)
#pragma unroll
        for (int ks = 0; ks < 4; ks++) {
            uint32_t ah[4], al[4];
            split2(S[2 * ks][0],     S[2 * ks][1],     ah[0], al[0]);
            split2(S[2 * ks][2],     S[2 * ks][3],     ah[1], al[1]);
            split2(S[2 * ks + 1][0], S[2 * ks + 1][1], ah[2], al[2]);
            split2(S[2 * ks + 1][2], S[2 * ks + 1][3], ah[3], al[3]);
#pragma unroll
            for (int jnp = 0; jnp < 4; jnp++) {
                uint32_t bh[4], bl[4];
                const uint32_t vaddr = va + ks * 16 * ASTR * 4 + jnp * 32;
                ldsm4t(bh, vaddr);
                ldsm4t(bl, vaddr + LO);
                mma16(O[2 * jnp], ah, bh);         mma16(O[2 * jnp], ah, bl);
                mma16(O[2 * jnp], al, bh);
                mma16(O[2 * jnp + 1], ah, bh + 2); mma16(O[2 * jnp + 1], ah, bl + 2);
                mma16(O[2 * jnp + 1], al, bh + 2);
            }
        }
        __syncthreads();
    }

    // ---- epilogue: normalize + store (float2)
    const int g2 = (lane >> 2);
    const float inv0 = 1.f / lrow0;
    const float inv1 = 1.f / lrow1;
    const int row0 = q0 + wm + g2;
#pragma unroll
    for (int jn = 0; jn < 8; jn++) {
        const int col = h * DHEAD + jn * 8 + 2 * tig;
        float2 v0, v1;
        v0.x = O[jn][0] * inv0; v0.y = O[jn][1] * inv0;
        v1.x = O[jn][2] * inv1; v1.y = O[jn][3] * inv1;
        *(float2*)(out + ((size_t)b * SLEN + row0) * DMODEL + col)     = v0;
        *(float2*)(out + ((size_t)b * SLEN + row0 + 8) * DMODEL + col) = v1;
    }
}

// ---------------------------------------------------------------------------
extern "C" void kernel_launch(void* const* d_in, const int* in_sizes, int n_in,
                              void* d_out, int out_size)
{
    const float* Q    = (const float*)d_in[0];
    const float* K    = (const float*)d_in[1];
    const float* V    = (const float*)d_in[2];
    const int*   mask = (const int*)d_in[3];
    const float* Wq   = (const float*)d_in[4];
    const float* bq   = (const float*)d_in[5];
    const float* Wk   = (const float*)d_in[6];
    const float* bk   = (const float*)d_in[7];
    const float* Wv   = (const float*)d_in[8];
    const float* bv   = (const float*)d_in[9];
    float* out = (float*)d_out;

    compact_mask<<<BATCH, 256>>>(mask);

    const dim3 tgrid(DMODEL / 32, DMODEL / 32, 3);
    wT_split<<<tgrid, dim3(32, 8)>>>(Wq, Wk, Wv);

    cudaFuncSetAttribute(proj_mma, cudaFuncAttributeMaxDynamicSharedMemorySize,
                         PROJ_SMEM);
    const dim3 pgrid(DMODEL / 128, (BATCH * SLEN) / 128, 3);
    proj_mma<<<pgrid, 256, PROJ_SMEM>>>(Q, K, V, bq, bk, bv);

    cudaFuncSetAttribute(attn_mma, cudaFuncAttributeMaxDynamicSharedMemorySize,
                         ATTN_SMEM);
    const dim3 agrid(SLEN / 128, NHEAD, BATCH);
    attn_mma<<<agrid, 256, ATTN_SMEM>>>(out);
}

// round 16
// speedup vs baseline: 1.5800x; 1.5800x over previous
#include <cuda_runtime.h>
#include <cuda_bf16.h>
#include <math.h>
#include <stdint.h>

#define BATCH  4
#define SLEN   2048
#define DMODEL 1024
#define NHEAD  16
#define DHEAD  64
// K is pre-scaled by ATT_SCALE * log2(e): softmax runs in exp2 domain.
#define K_SCALE 0.1803368801111204f   // 0.125 * 1.4426950408889634

// ---------------------------------------------------------------------------
// Device scratch (no cudaMalloc allowed). All projected tensors stored as
// pre-split bf16 hi/lo pairs; K pre-scaled. W^T pre-split too.
// ---------------------------------------------------------------------------
#define NTOK (BATCH * SLEN * DMODEL)
__device__ __nv_bfloat16 g_qh[NTOK], g_ql[NTOK];
__device__ __nv_bfloat16 g_kh[NTOK], g_kl[NTOK];
__device__ __nv_bfloat16 g_vh[NTOK], g_vl[NTOK];
__device__ __nv_bfloat16 g_wth[3 * DMODEL * DMODEL], g_wtl[3 * DMODEL * DMODEL];
__device__ int g_idx[BATCH * SLEN];
__device__ int g_nv[BATCH];

// ---------------------------------------------------------------------------
// Helpers
// ---------------------------------------------------------------------------
__device__ __forceinline__ void mma16(float c[4], const uint32_t a[4],
                                      const uint32_t b[2]) {
    asm volatile(
        "mma.sync.aligned.m16n8k16.row.col.f32.bf16.bf16.f32 "
        "{%0,%1,%2,%3}, {%4,%5,%6,%7}, {%8,%9}, {%0,%1,%2,%3};"
        : "+f"(c[0]), "+f"(c[1]), "+f"(c[2]), "+f"(c[3])
        : "r"(a[0]), "r"(a[1]), "r"(a[2]), "r"(a[3]),
          "r"(b[0]), "r"(b[1]));
}

__device__ __forceinline__ void ldsm4(uint32_t r[4], uint32_t addr) {
    asm volatile(
        "ldmatrix.sync.aligned.m8n8.x4.shared.b16 {%0,%1,%2,%3}, [%4];"
        : "=r"(r[0]), "=r"(r[1]), "=r"(r[2]), "=r"(r[3]) : "r"(addr));
}

__device__ __forceinline__ void ldsm4t(uint32_t r[4], uint32_t addr) {
    asm volatile(
        "ldmatrix.sync.aligned.m8n8.x4.trans.shared.b16 {%0,%1,%2,%3}, [%4];"
        : "=r"(r[0]), "=r"(r[1]), "=r"(r[2]), "=r"(r[3]) : "r"(addr));
}

__device__ __forceinline__ uint32_t sptr(const void* p) {
    return (uint32_t)__cvta_generic_to_shared(p);
}

__device__ __forceinline__ void cpa16(uint32_t s, const void* g) {
    asm volatile("cp.async.cg.shared.global [%0], [%1], 16;" :: "r"(s), "l"(g));
}
#define CP_COMMIT() asm volatile("cp.async.commit_group;" ::: "memory")
#define CP_WAIT(n)  asm volatile("cp.async.wait_group %0;" :: "n"(n) : "memory")

__device__ __forceinline__ float ex2(float x) {
    float r;
    asm("ex2.approx.f32 %0, %1;" : "=f"(r) : "f"(x));
    return r;
}

__device__ __forceinline__ void split2(float x0, float x1, uint32_t& h,
                                       uint32_t& l) {
    __nv_bfloat162 hb = __floats2bfloat162_rn(x0, x1);
    const float2 hf = __bfloat1622float2(hb);
    __nv_bfloat162 lb = __floats2bfloat162_rn(x0 - hf.x, x1 - hf.y);
    h = *reinterpret_cast<uint32_t*>(&hb);
    l = *reinterpret_cast<uint32_t*>(&lb);
}

// ---------------------------------------------------------------------------
// Mask compaction: per batch, prefix-scan the key-padding mask.
// ---------------------------------------------------------------------------
__global__ __launch_bounds__(256)
void compact_mask(const int* __restrict__ mask)
{
    __shared__ int part[256];
    const int b   = blockIdx.x;
    const int tid = threadIdx.x;
    const int* mb = mask + b * SLEN;

    int loc[8];
    int cnt = 0;
#pragma unroll
    for (int e = 0; e < 8; e++) {
        loc[e] = cnt;
        cnt += (mb[tid * 8 + e] != 0);
    }
    part[tid] = cnt;
    __syncthreads();
#pragma unroll
    for (int off = 1; off < 256; off <<= 1) {
        const int v = (tid >= off) ? part[tid - off] : 0;
        __syncthreads();
        part[tid] += v;
        __syncthreads();
    }
    const int excl = part[tid] - cnt;
#pragma unroll
    for (int e = 0; e < 8; e++) {
        if (mb[tid * 8 + e] != 0)
            g_idx[b * SLEN + excl + loc[e]] = tid * 8 + e;
    }
    const int total = part[255];
    if (tid == 0) g_nv[b] = total;
    __syncthreads();
    for (int j = total + tid; j < SLEN; j += 256)
        g_idx[b * SLEN + j] = 0;
}

// ---------------------------------------------------------------------------
// W^T prep: transpose + bf16 hi/lo split all three weight matrices.
// ---------------------------------------------------------------------------
__global__ __launch_bounds__(256)
void wT_split(const float* __restrict__ W0, const float* __restrict__ W1,
              const float* __restrict__ W2)
{
    __shared__ float t[32][33];
    const int z  = blockIdx.z;
    const float* W = (z == 0) ? W0 : (z == 1) ? W1 : W2;
    const int x  = blockIdx.x * 32 + threadIdx.x;
    const int y0 = blockIdx.y * 32;
#pragma unroll
    for (int i = threadIdx.y; i < 32; i += 8)
        t[i][threadIdx.x] = W[(size_t)(y0 + i) * DMODEL + x];
    __syncthreads();
    const int ko = y0 + threadIdx.x;
    const int no = blockIdx.x * 32;
    __nv_bfloat16* th = g_wth + (size_t)z * DMODEL * DMODEL;
    __nv_bfloat16* tl = g_wtl + (size_t)z * DMODEL * DMODEL;
#pragma unroll
    for (int i = threadIdx.y; i < 32; i += 8) {
        const float v = t[threadIdx.x][i];
        const __nv_bfloat16 h = __float2bfloat16(v);
        th[(size_t)(no + i) * DMODEL + ko] = h;
        tl[(size_t)(no + i) * DMODEL + ko] =
            __float2bfloat16(v - __bfloat162float(h));
    }
}

// ---------------------------------------------------------------------------
// Fused projection GEMMs, BK=64, 16 phases (R12 structure).
// z=0: Q. z=1: K (pre-scaled by K_SCALE). z=2: V (gathered via g_idx).
// ---------------------------------------------------------------------------
#define PSTR 36
#define PROJ_SMEM (4 * 128 * PSTR * 4)   // 73728 bytes

__global__ __launch_bounds__(256, 2)
void proj_mma(const float* __restrict__ X0, const float* __restrict__ X1,
              const float* __restrict__ X2,
              const float* __restrict__ b0, const float* __restrict__ b1,
              const float* __restrict__ b2)
{
    extern __shared__ uint32_t smw[];
    uint32_t* Ah = smw;                    // [128][PSTR]
    uint32_t* Al = Ah + 128 * PSTR;
    uint32_t* Bh = Al + 128 * PSTR;
    uint32_t* Bl = Bh + 128 * PSTR;

    const int z = blockIdx.z;
    const float* X    = (z == 0) ? X0 : (z == 1) ? X1 : X2;
    const float* bias = (z == 0) ? b0 : (z == 1) ? b1 : b2;
    __nv_bfloat16* Yh = (z == 0) ? g_qh : (z == 1) ? g_kh : g_vh;
    __nv_bfloat16* Yl = (z == 0) ? g_ql : (z == 1) ? g_kl : g_vl;
    const __nv_bfloat16* WTh = g_wth + (size_t)z * DMODEL * DMODEL;
    const __nv_bfloat16* WTl = g_wtl + (size_t)z * DMODEL * DMODEL;
    const float oscale = (z == 1) ? K_SCALE : 1.0f;

    const int m0   = blockIdx.y * 128;
    const int n0   = blockIdx.x * 128;
    const int bb   = m0 >> 11;
    const int mloc = m0 & 2047;

    const int nvb = (z == 0) ? SLEN : g_nv[bb];
    if (mloc >= nvb) return;
    const int* idxb = g_idx + bb * SLEN;

    const int tid  = threadIdx.x;
    const int lane = tid & 31;
    const int w    = tid >> 5;
    const int g    = lane >> 2;
    const int tig  = lane & 3;
    const int wm   = (w >> 2) * 64;
    const int wn   = (w & 3) * 32;

    const int lane15  = lane & 15;
    const int halfsel = (lane >> 4) & 1;
    const int krow    = (lane & 7) + ((lane & 16) >> 1);
    const int kcol    = (lane & 8) >> 1;

    const uint32_t pa = sptr(Ah) + ((wm + lane15) * PSTR + halfsel * 4) * 4;
    const uint32_t pb = sptr(Bh) + ((wn + krow) * PSTR + kcol) * 4;
    const uint32_t ALO = 128 * PSTR * 4;
    const uint32_t BLO = 128 * PSTR * 4;

    // source row for each of this thread's 8 A-tile rows (gathered for K/V)
    int srow[8];
#pragma unroll
    for (int it = 0; it < 8; it++) {
        const int r = (tid + it * 256) >> 4;
        if (z == 0) srow[it] = m0 + r;
        else {
            const int j = mloc + r;
            srow[it] = (bb << 11) + ((j < nvb) ? idxb[j] : idxb[0]);
        }
    }

    const uint32_t sBh = sptr(Bh), sBl = sptr(Bl);

    float acc[4][4][4];
#pragma unroll
    for (int i = 0; i < 4; i++)
#pragma unroll
        for (int j = 0; j < 4; j++)
#pragma unroll
            for (int r = 0; r < 4; r++) acc[i][j][r] = 0.f;

    for (int k0 = 0; k0 < DMODEL; k0 += 64) {
        // ---- A tile: fp32 X rows (64 k), split to bf16 hi/lo
#pragma unroll
        for (int it = 0; it < 8; it++) {
            const int idx = tid + it * 256;
            const int r = idx >> 4, c = (idx & 15) << 2;
            const float4 v = *(const float4*)(X + (size_t)srow[it] * DMODEL + k0 + c);
            uint32_t h0, l0, h1, l1;
            split2(v.x, v.y, h0, l0);
            split2(v.z, v.w, h1, l1);
            *(uint2*)&Ah[r * PSTR + (c >> 1)] = make_uint2(h0, h1);
            *(uint2*)&Al[r * PSTR + (c >> 1)] = make_uint2(l0, l1);
        }
        // ---- B tile: pure cp.async copy of pre-split W^T (64 k)
#pragma unroll
        for (int it = 0; it < 4; it++) {
            const int idx = tid + it * 256;
            const int n = idx >> 3, ch = idx & 7;
            const size_t gg = (size_t)(n0 + n) * DMODEL + k0 + ch * 8;
            const uint32_t sm = (n * PSTR + ch * 4) * 4;
            cpa16(sBh + sm, WTh + gg);
            cpa16(sBl + sm, WTl + gg);
        }
        CP_COMMIT();
        CP_WAIT(0);
        __syncthreads();

#pragma unroll
        for (int ks = 0; ks < 4; ks++) {
            uint32_t bh0[4], bl0[4], bh1[4], bl1[4];
            ldsm4(bh0, pb + ks * 32);
            ldsm4(bl0, pb + ks * 32 + BLO);
            ldsm4(bh1, pb + 16 * PSTR * 4 + ks * 32);
            ldsm4(bl1, pb + 16 * PSTR * 4 + ks * 32 + BLO);
#pragma unroll
            for (int i = 0; i < 4; i++) {
                uint32_t ah[4], al[4];
                ldsm4(ah, pa + i * 16 * PSTR * 4 + ks * 32);
                ldsm4(al, pa + i * 16 * PSTR * 4 + ks * 32 + ALO);
                mma16(acc[i][0], ah, bh0);     mma16(acc[i][0], ah, bl0);
                mma16(acc[i][0], al, bh0);
                mma16(acc[i][1], ah, bh0 + 2); mma16(acc[i][1], ah, bl0 + 2);
                mma16(acc[i][1], al, bh0 + 2);
                mma16(acc[i][2], ah, bh1);     mma16(acc[i][2], ah, bl1);
                mma16(acc[i][2], al, bh1);
                mma16(acc[i][3], ah, bh1 + 2); mma16(acc[i][3], ah, bl1 + 2);
                mma16(acc[i][3], al, bh1 + 2);
            }
        }
        __syncthreads();
    }

    // ---- epilogue: (+bias) * oscale, split to bf16 hi/lo, store
#pragma unroll
    for (int j = 0; j < 4; j++) {
        const int col = n0 + wn + j * 8 + 2 * tig;
        const float bx = bias[col], by = bias[col + 1];
#pragma unroll
        for (int i = 0; i < 4; i++) {
            const int r0 = m0 + wm + i * 16 + g;
            uint32_t h0, l0, h1, l1;
            split2((acc[i][j][0] + bx) * oscale, (acc[i][j][1] + by) * oscale,
                   h0, l0);
            split2((acc[i][j][2] + bx) * oscale, (acc[i][j][3] + by) * oscale,
                   h1, l1);
            *(uint32_t*)&Yh[(size_t)r0 * DMODEL + col]       = h0;
            *(uint32_t*)&Yl[(size_t)r0 * DMODEL + col]       = l0;
            *(uint32_t*)&Yh[(size_t)(r0 + 8) * DMODEL + col] = h1;
            *(uint32_t*)&Yl[(size_t)(r0 + 8) * DMODEL + col] = l1;
        }
    }
}

// ---------------------------------------------------------------------------
// Flash attention over PACKED pre-split bf16 keys, double-buffered K/V.
// Scores arrive in log2 domain (K pre-scaled by 0.125*log2e) -> bare ex2.
// ---------------------------------------------------------------------------
#define ASTR   36
#define KVW    (4 * 64 * ASTR)
#define ATTN_SMEM ((2 * 128 * ASTR + 2 * KVW) * 4)   // 110592 bytes

__global__ __launch_bounds__(256, 2)
void attn_mma(float* __restrict__ out)
{
    extern __shared__ uint32_t smw[];
    const int tid  = threadIdx.x;
    const int lane = tid & 31;
    const int w    = tid >> 5;
    const int tig  = lane & 3;
    const int wm   = w * 16;
    const int q0   = blockIdx.x << 7;
    const int h    = blockIdx.y;
    const int b    = blockIdx.z;

    const size_t base = (size_t)b * SLEN * DMODEL + h * DHEAD;
    const __nv_bfloat16* qhg = g_qh + base;
    const __nv_bfloat16* qlg = g_ql + base;
    const __nv_bfloat16* khg = g_kh + base;
    const __nv_bfloat16* klg = g_kl + base;
    const __nv_bfloat16* vhg = g_vh + base;
    const __nv_bfloat16* vlg = g_vl + base;
    const int nvb   = g_nv[b];
    const int ntile = (nvb + 63) >> 6;

    const int lane15  = lane & 15;
    const int halfsel = (lane >> 4) & 1;
    const int krow    = (lane & 7) + ((lane & 16) >> 1);
    const int kcol    = (lane & 8) >> 1;

    const uint32_t sbase  = sptr(smw);
    const uint32_t kvbase = sbase + 9216u * 4;
    const uint32_t qa  = sbase + ((wm + lane15) * ASTR + halfsel * 4) * 4;
    const uint32_t QLO = 4608u * 4;
    const uint32_t kaB = (krow * ASTR + kcol) * 4;
    const uint32_t vaB = 4608u * 4 + (lane15 * ASTR + halfsel * 4) * 4;
    const uint32_t LO  = 2304u * 4;

    // ---- Q fill (cp.async)
#pragma unroll
    for (int it = 0; it < 4; it++) {
        const int idx = tid + it * 256;
        const int r = idx >> 3, ch = idx & 7;
        const size_t gg = (size_t)(q0 + r) * DMODEL + ch * 8;
        const uint32_t sm = (r * ASTR + ch * 4) * 4;
        cpa16(sbase + sm, qhg + gg);
        cpa16(sbase + QLO + sm, qlg + gg);
    }
    CP_COMMIT();

    // ---- K/V prefetch tile 0
#pragma unroll
    for (int it = 0; it < 2; it++) {
        const int idx = tid + it * 256;
        const int r = idx >> 3, ch = idx & 7;
        const size_t gg = (size_t)r * DMODEL + ch * 8;
        const uint32_t sm = (r * ASTR + ch * 4) * 4;
        cpa16(kvbase + sm,          khg + gg);
        cpa16(kvbase + LO + sm,     klg + gg);
        cpa16(kvbase + 2 * LO + sm, vhg + gg);
        cpa16(kvbase + 3 * LO + sm, vlg + gg);
    }
    CP_COMMIT();

    float O[8][4];
#pragma unroll
    for (int j = 0; j < 8; j++)
#pragma unroll
        for (int r = 0; r < 4; r++) O[j][r] = 0.f;
    float mrow0 = -1e30f, mrow1 = -1e30f, lrow0 = 0.f, lrow1 = 0.f;

    const unsigned FULL = 0xffffffffu;

    for (int t = 0; t < ntile; t++) {
        if (t + 1 < ntile) {
            const int k1 = (t + 1) << 6;
            const uint32_t st = kvbase + (uint32_t)((t + 1) & 1) * (KVW * 4);
#pragma unroll
            for (int it = 0; it < 2; it++) {
                const int idx = tid + it * 256;
                const int r = idx >> 3, ch = idx & 7;
                const size_t gg = (size_t)(k1 + r) * DMODEL + ch * 8;
                const uint32_t sm = (r * ASTR + ch * 4) * 4;
                cpa16(st + sm,          khg + gg);
                cpa16(st + LO + sm,     klg + gg);
                cpa16(st + 2 * LO + sm, vhg + gg);
                cpa16(st + 3 * LO + sm, vlg + gg);
            }
            CP_COMMIT();
            CP_WAIT(1);
        } else {
            CP_WAIT(0);
        }
        __syncthreads();

        const int k0 = t << 6;
        const uint32_t kvb = kvbase + (uint32_t)(t & 1) * (KVW * 4);
        const uint32_t ka = kvb + kaB;
        const uint32_t va = kvb + vaB;

        // ---- S = Q @ K^T (bf16x3; K pre-scaled into log2 domain)
        float S[8][4];
#pragma unroll
        for (int j = 0; j < 8; j++)
#pragma unroll
            for (int r = 0; r < 4; r++) S[j][r] = 0.f;

#pragma unroll
        for (int ks = 0; ks < 4; ks++) {
            uint32_t ah[4], al[4];
            ldsm4(ah, qa + ks * 32);
            ldsm4(al, qa + ks * 32 + QLO);
#pragma unroll
            for (int jp = 0; jp < 4; jp++) {
                uint32_t bh[4], bl[4];
                const uint32_t kaddr = ka + jp * 16 * ASTR * 4 + ks * 32;
                ldsm4(bh, kaddr);
                ldsm4(bl, kaddr + LO);
                mma16(S[2 * jp], ah, bh);         mma16(S[2 * jp], ah, bl);
                mma16(S[2 * jp], al, bh);
                mma16(S[2 * jp + 1], ah, bh + 2); mma16(S[2 * jp + 1], ah, bl + 2);
                mma16(S[2 * jp + 1], al, bh + 2);
            }
        }

        // ---- tail mask only on the final partial tile
        float mx0 = -1e30f, mx1 = -1e30f;
        if (k0 + 64 > nvb) {
#pragma unroll
            for (int j = 0; j < 8; j++) {
                const int c = k0 + j * 8 + 2 * tig;
                if (c >= nvb)     { S[j][0] = -1e9f; S[j][2] = -1e9f; }
                if (c + 1 >= nvb) { S[j][1] = -1e9f; S[j][3] = -1e9f; }
            }
        }
#pragma unroll
        for (int j = 0; j < 8; j++) {
            mx0 = fmaxf(mx0, fmaxf(S[j][0], S[j][1]));
            mx1 = fmaxf(mx1, fmaxf(S[j][2], S[j][3]));
        }
        mx0 = fmaxf(mx0, __shfl_xor_sync(FULL, mx0, 1));
        mx0 = fmaxf(mx0, __shfl_xor_sync(FULL, mx0, 2));
        mx1 = fmaxf(mx1, __shfl_xor_sync(FULL, mx1, 1));
        mx1 = fmaxf(mx1, __shfl_xor_sync(FULL, mx1, 2));

        const float mnew0 = fmaxf(mrow0, mx0);
        const float mnew1 = fmaxf(mrow1, mx1);
        const float fac0  = ex2(mrow0 - mnew0);
        const float fac1  = ex2(mrow1 - mnew1);

        float sum0 = 0.f, sum1 = 0.f;
#pragma unroll
        for (int j = 0; j < 8; j++) {
            S[j][0] = ex2(S[j][0] - mnew0);
            S[j][1] = ex2(S[j][1] - mnew0);
            S[j][2] = ex2(S[j][2] - mnew1);
            S[j][3] = ex2(S[j][3] - mnew1);
            sum0 += S[j][0] + S[j][1];
            sum1 += S[j][2] + S[j][3];
        }
        sum0 += __shfl_xor_sync(FULL, sum0, 1);
        sum0 += __shfl_xor_sync(FULL, sum0, 2);
        sum1 += __shfl_xor_sync(FULL, sum1, 1);
        sum1 += __shfl_xor_sync(FULL, sum1, 2);

        lrow0 = lrow0 * fac0 + sum0;
        lrow1 = lrow1 * fac1 + sum1;
        mrow0 = mnew0;
        mrow1 = mnew1;

#pragma unroll
        for (int j = 0; j < 8; j++) {
            O[j][0] *= fac0; O[j][1] *= fac0;
            O[j][2] *= fac1; O[j][3] *= fac1;
        }

        // ---- O += P @ V (P in-register cvt; V via ldmatrix.trans)
#pragma unroll
        for (int ks = 0; ks < 4; ks++) {
            uint32_t ah[4], al[4];
            split2(S[2 * ks][0],     S[2 * ks][1],     ah[0], al[0]);
            split2(S[2 * ks][2],     S[2 * ks][3],     ah[1], al[1]);
            split2(S[2 * ks + 1][0], S[2 * ks + 1][1], ah[2], al[2]);
            split2(S[2 * ks + 1][2], S[2 * ks + 1][3], ah[3], al[3]);
#pragma unroll
            for (int jnp = 0; jnp < 4; jnp++) {
                uint32_t bh[4], bl[4];
                const uint32_t vaddr = va + ks * 16 * ASTR * 4 + jnp * 32;
                ldsm4t(bh, vaddr);
                ldsm4t(bl, vaddr + LO);
                mma16(O[2 * jnp], ah, bh);         mma16(O[2 * jnp], ah, bl);
                mma16(O[2 * jnp], al, bh);
                mma16(O[2 * jnp + 1], ah, bh + 2); mma16(O[2 * jnp + 1], ah, bl + 2);
                mma16(O[2 * jnp + 1], al, bh + 2);
            }
        }
        __syncthreads();
    }

    // ---- epilogue: normalize + store (float2)
    const int g2 = (lane >> 2);
    const float inv0 = 1.f / lrow0;
    const float inv1 = 1.f / lrow1;
    const int row0 = q0 + wm + g2;
#pragma unroll
    for (int jn = 0; jn < 8; jn++) {
        const int col = h * DHEAD + jn * 8 + 2 * tig;
        float2 v0, v1;
        v0.x = O[jn][0] * inv0; v0.y = O[jn][1] * inv0;
        v1.x = O[jn][2] * inv1; v1.y = O[jn][3] * inv1;
        *(float2*)(out + ((size_t)b * SLEN + row0) * DMODEL + col)     = v0;
        *(float2*)(out + ((size_t)b * SLEN + row0 + 8) * DMODEL + col) = v1;
    }
}

// ---------------------------------------------------------------------------
extern "C" void kernel_launch(void* const* d_in, const int* in_sizes, int n_in,
                              void* d_out, int out_size)
{
    const float* Q    = (const float*)d_in[0];
    const float* K    = (const float*)d_in[1];
    const float* V    = (const float*)d_in[2];
    const int*   mask = (const int*)d_in[3];
    const float* Wq   = (const float*)d_in[4];
    const float* bq   = (const float*)d_in[5];
    const float* Wk   = (const float*)d_in[6];
    const float* bk   = (const float*)d_in[7];
    const float* Wv   = (const float*)d_in[8];
    const float* bv   = (const float*)d_in[9];
    float* out = (float*)d_out;

    compact_mask<<<BATCH, 256>>>(mask);

    const dim3 tgrid(DMODEL / 32, DMODEL / 32, 3);
    wT_split<<<tgrid, dim3(32, 8)>>>(Wq, Wk, Wv);

    cudaFuncSetAttribute(proj_mma, cudaFuncAttributeMaxDynamicSharedMemorySize,
                         PROJ_SMEM);
    const dim3 pgrid(DMODEL / 128, (BATCH * SLEN) / 128, 3);
    proj_mma<<<pgrid, 256, PROJ_SMEM>>>(Q, K, V, bq, bk, bv);

    cudaFuncSetAttribute(attn_mma, cudaFuncAttributeMaxDynamicSharedMemorySize,
                         ATTN_SMEM);
    const dim3 agrid(SLEN / 128, NHEAD, BATCH);
    attn_mma<<<agrid, 256, ATTN_SMEM>>>(out);
}

// round 17
// speedup vs baseline: 1.6754x; 1.0604x over previous
#include <cuda_runtime.h>
#include <cuda_bf16.h>
#include <cuda_fp16.h>
#include <math.h>
#include <stdint.h>

#define BATCH  4
#define SLEN   2048
#define DMODEL 1024
#define NHEAD  16
#define DHEAD  64
// K is pre-scaled by ATT_SCALE * log2(e): softmax runs in exp2 domain.
#define K_SCALE 0.1803368801111204f   // 0.125 * 1.4426950408889634

// ---------------------------------------------------------------------------
// Device scratch (no cudaMalloc allowed). Q/K stored as pre-split bf16 hi/lo;
// V stored as pre-split FP16 hi/lo (PV runs 2-term fp16). W^T pre-split bf16.
// ---------------------------------------------------------------------------
#define NTOK (BATCH * SLEN * DMODEL)
__device__ __nv_bfloat16 g_qh[NTOK], g_ql[NTOK];
__device__ __nv_bfloat16 g_kh[NTOK], g_kl[NTOK];
__device__ __nv_bfloat16 g_vh[NTOK], g_vl[NTOK];   // holds fp16 bits
__device__ __nv_bfloat16 g_wth[3 * DMODEL * DMODEL], g_wtl[3 * DMODEL * DMODEL];
__device__ int g_idx[BATCH * SLEN];
__device__ int g_nv[BATCH];

// ---------------------------------------------------------------------------
// Helpers
// ---------------------------------------------------------------------------
__device__ __forceinline__ void mma16(float c[4], const uint32_t a[4],
                                      const uint32_t b[2]) {
    asm volatile(
        "mma.sync.aligned.m16n8k16.row.col.f32.bf16.bf16.f32 "
        "{%0,%1,%2,%3}, {%4,%5,%6,%7}, {%8,%9}, {%0,%1,%2,%3};"
        : "+f"(c[0]), "+f"(c[1]), "+f"(c[2]), "+f"(c[3])
        : "r"(a[0]), "r"(a[1]), "r"(a[2]), "r"(a[3]),
          "r"(b[0]), "r"(b[1]));
}

__device__ __forceinline__ void mma16h(float c[4], const uint32_t a[4],
                                       const uint32_t b[2]) {
    asm volatile(
        "mma.sync.aligned.m16n8k16.row.col.f32.f16.f16.f32 "
        "{%0,%1,%2,%3}, {%4,%5,%6,%7}, {%8,%9}, {%0,%1,%2,%3};"
        : "+f"(c[0]), "+f"(c[1]), "+f"(c[2]), "+f"(c[3])
        : "r"(a[0]), "r"(a[1]), "r"(a[2]), "r"(a[3]),
          "r"(b[0]), "r"(b[1]));
}

__device__ __forceinline__ void ldsm4(uint32_t r[4], uint32_t addr) {
    asm volatile(
        "ldmatrix.sync.aligned.m8n8.x4.shared.b16 {%0,%1,%2,%3}, [%4];"
        : "=r"(r[0]), "=r"(r[1]), "=r"(r[2]), "=r"(r[3]) : "r"(addr));
}

__device__ __forceinline__ void ldsm4t(uint32_t r[4], uint32_t addr) {
    asm volatile(
        "ldmatrix.sync.aligned.m8n8.x4.trans.shared.b16 {%0,%1,%2,%3}, [%4];"
        : "=r"(r[0]), "=r"(r[1]), "=r"(r[2]), "=r"(r[3]) : "r"(addr));
}

__device__ __forceinline__ uint32_t sptr(const void* p) {
    return (uint32_t)__cvta_generic_to_shared(p);
}

__device__ __forceinline__ void cpa16(uint32_t s, const void* g) {
    asm volatile("cp.async.cg.shared.global [%0], [%1], 16;" :: "r"(s), "l"(g));
}
#define CP_COMMIT() asm volatile("cp.async.commit_group;" ::: "memory")
#define CP_WAIT(n)  asm volatile("cp.async.wait_group %0;" :: "n"(n) : "memory")

__device__ __forceinline__ float ex2(float x) {
    float r;
    asm("ex2.approx.f32 %0, %1;" : "=f"(r) : "f"(x));
    return r;
}

__device__ __forceinline__ void split2(float x0, float x1, uint32_t& h,
                                       uint32_t& l) {
    __nv_bfloat162 hb = __floats2bfloat162_rn(x0, x1);
    const float2 hf = __bfloat1622float2(hb);
    __nv_bfloat162 lb = __floats2bfloat162_rn(x0 - hf.x, x1 - hf.y);
    h = *reinterpret_cast<uint32_t*>(&hb);
    l = *reinterpret_cast<uint32_t*>(&lb);
}

// FP16 hi/lo split (for V)
__device__ __forceinline__ void split2h(float x0, float x1, uint32_t& h,
                                        uint32_t& l) {
    __half2 hb = __floats2half2_rn(x0, x1);
    const float2 hf = __half22float2(hb);
    __half2 lb = __floats2half2_rn(x0 - hf.x, x1 - hf.y);
    h = *reinterpret_cast<uint32_t*>(&hb);
    l = *reinterpret_cast<uint32_t*>(&lb);
}

__device__ __forceinline__ uint32_t packh2(float x0, float x1) {
    __half2 p = __floats2half2_rn(x0, x1);
    return *reinterpret_cast<uint32_t*>(&p);
}

// ---------------------------------------------------------------------------
// Mask compaction: per batch, prefix-scan the key-padding mask.
// ---------------------------------------------------------------------------
__global__ __launch_bounds__(256)
void compact_mask(const int* __restrict__ mask)
{
    __shared__ int part[256];
    const int b   = blockIdx.x;
    const int tid = threadIdx.x;
    const int* mb = mask + b * SLEN;

    int loc[8];
    int cnt = 0;
#pragma unroll
    for (int e = 0; e < 8; e++) {
        loc[e] = cnt;
        cnt += (mb[tid * 8 + e] != 0);
    }
    part[tid] = cnt;
    __syncthreads();
#pragma unroll
    for (int off = 1; off < 256; off <<= 1) {
        const int v = (tid >= off) ? part[tid - off] : 0;
        __syncthreads();
        part[tid] += v;
        __syncthreads();
    }
    const int excl = part[tid] - cnt;
#pragma unroll
    for (int e = 0; e < 8; e++) {
        if (mb[tid * 8 + e] != 0)
            g_idx[b * SLEN + excl + loc[e]] = tid * 8 + e;
    }
    const int total = part[255];
    if (tid == 0) g_nv[b] = total;
    __syncthreads();
    for (int j = total + tid; j < SLEN; j += 256)
        g_idx[b * SLEN + j] = 0;
}

// ---------------------------------------------------------------------------
// W^T prep: transpose + bf16 hi/lo split all three weight matrices.
// ---------------------------------------------------------------------------
__global__ __launch_bounds__(256)
void wT_split(const float* __restrict__ W0, const float* __restrict__ W1,
              const float* __restrict__ W2)
{
    __shared__ float t[32][33];
    const int z  = blockIdx.z;
    const float* W = (z == 0) ? W0 : (z == 1) ? W1 : W2;
    const int x  = blockIdx.x * 32 + threadIdx.x;
    const int y0 = blockIdx.y * 32;
#pragma unroll
    for (int i = threadIdx.y; i < 32; i += 8)
        t[i][threadIdx.x] = W[(size_t)(y0 + i) * DMODEL + x];
    __syncthreads();
    const int ko = y0 + threadIdx.x;
    const int no = blockIdx.x * 32;
    __nv_bfloat16* th = g_wth + (size_t)z * DMODEL * DMODEL;
    __nv_bfloat16* tl = g_wtl + (size_t)z * DMODEL * DMODEL;
#pragma unroll
    for (int i = threadIdx.y; i < 32; i += 8) {
        const float v = t[threadIdx.x][i];
        const __nv_bfloat16 h = __float2bfloat16(v);
        th[(size_t)(no + i) * DMODEL + ko] = h;
        tl[(size_t)(no + i) * DMODEL + ko] =
            __float2bfloat16(v - __bfloat162float(h));
    }
}

// ---------------------------------------------------------------------------
// Fused projection GEMMs, BK=64, 16 phases (R12 structure).
// z=0: Q (bf16 out). z=1: K (bf16 out, pre-scaled). z=2: V (FP16 out, gathered).
// ---------------------------------------------------------------------------
#define PSTR 36
#define PROJ_SMEM (4 * 128 * PSTR * 4)   // 73728 bytes

__global__ __launch_bounds__(256, 2)
void proj_mma(const float* __restrict__ X0, const float* __restrict__ X1,
              const float* __restrict__ X2,
              const float* __restrict__ b0, const float* __restrict__ b1,
              const float* __restrict__ b2)
{
    extern __shared__ uint32_t smw[];
    uint32_t* Ah = smw;                    // [128][PSTR]
    uint32_t* Al = Ah + 128 * PSTR;
    uint32_t* Bh = Al + 128 * PSTR;
    uint32_t* Bl = Bh + 128 * PSTR;

    const int z = blockIdx.z;
    const float* X    = (z == 0) ? X0 : (z == 1) ? X1 : X2;
    const float* bias = (z == 0) ? b0 : (z == 1) ? b1 : b2;
    __nv_bfloat16* Yh = (z == 0) ? g_qh : (z == 1) ? g_kh : g_vh;
    __nv_bfloat16* Yl = (z == 0) ? g_ql : (z == 1) ? g_kl : g_vl;
    const __nv_bfloat16* WTh = g_wth + (size_t)z * DMODEL * DMODEL;
    const __nv_bfloat16* WTl = g_wtl + (size_t)z * DMODEL * DMODEL;
    const float oscale = (z == 1) ? K_SCALE : 1.0f;

    const int m0   = blockIdx.y * 128;
    const int n0   = blockIdx.x * 128;
    const int bb   = m0 >> 11;
    const int mloc = m0 & 2047;

    const int nvb = (z == 0) ? SLEN : g_nv[bb];
    if (mloc >= nvb) return;
    const int* idxb = g_idx + bb * SLEN;

    const int tid  = threadIdx.x;
    const int lane = tid & 31;
    const int w    = tid >> 5;
    const int g    = lane >> 2;
    const int tig  = lane & 3;
    const int wm   = (w >> 2) * 64;
    const int wn   = (w & 3) * 32;

    const int lane15  = lane & 15;
    const int halfsel = (lane >> 4) & 1;
    const int krow    = (lane & 7) + ((lane & 16) >> 1);
    const int kcol    = (lane & 8) >> 1;

    const uint32_t pa = sptr(Ah) + ((wm + lane15) * PSTR + halfsel * 4) * 4;
    const uint32_t pb = sptr(Bh) + ((wn + krow) * PSTR + kcol) * 4;
    const uint32_t ALO = 128 * PSTR * 4;
    const uint32_t BLO = 128 * PSTR * 4;

    // source row for each of this thread's 8 A-tile rows (gathered for K/V)
    int srow[8];
#pragma unroll
    for (int it = 0; it < 8; it++) {
        const int r = (tid + it * 256) >> 4;
        if (z == 0) srow[it] = m0 + r;
        else {
            const int j = mloc + r;
            srow[it] = (bb << 11) + ((j < nvb) ? idxb[j] : idxb[0]);
        }
    }

    const uint32_t sBh = sptr(Bh), sBl = sptr(Bl);

    float acc[4][4][4];
#pragma unroll
    for (int i = 0; i < 4; i++)
#pragma unroll
        for (int j = 0; j < 4; j++)
#pragma unroll
            for (int r = 0; r < 4; r++) acc[i][j][r] = 0.f;

    for (int k0 = 0; k0 < DMODEL; k0 += 64) {
        // ---- A tile: fp32 X rows (64 k), split to bf16 hi/lo
#pragma unroll
        for (int it = 0; it < 8; it++) {
            const int idx = tid + it * 256;
            const int r = idx >> 4, c = (idx & 15) << 2;
            const float4 v = *(const float4*)(X + (size_t)srow[it] * DMODEL + k0 + c);
            uint32_t h0, l0, h1, l1;
            split2(v.x, v.y, h0, l0);
            split2(v.z, v.w, h1, l1);
            *(uint2*)&Ah[r * PSTR + (c >> 1)] = make_uint2(h0, h1);
            *(uint2*)&Al[r * PSTR + (c >> 1)] = make_uint2(l0, l1);
        }
        // ---- B tile: pure cp.async copy of pre-split W^T (64 k)
#pragma unroll
        for (int it = 0; it < 4; it++) {
            const int idx = tid + it * 256;
            const int n = idx >> 3, ch = idx & 7;
            const size_t gg = (size_t)(n0 + n) * DMODEL + k0 + ch * 8;
            const uint32_t sm = (n * PSTR + ch * 4) * 4;
            cpa16(sBh + sm, WTh + gg);
            cpa16(sBl + sm, WTl + gg);
        }
        CP_COMMIT();
        CP_WAIT(0);
        __syncthreads();

#pragma unroll
        for (int ks = 0; ks < 4; ks++) {
            uint32_t bh0[4], bl0[4], bh1[4], bl1[4];
            ldsm4(bh0, pb + ks * 32);
            ldsm4(bl0, pb + ks * 32 + BLO);
            ldsm4(bh1, pb + 16 * PSTR * 4 + ks * 32);
            ldsm4(bl1, pb + 16 * PSTR * 4 + ks * 32 + BLO);
#pragma unroll
            for (int i = 0; i < 4; i++) {
                uint32_t ah[4], al[4];
                ldsm4(ah, pa + i * 16 * PSTR * 4 + ks * 32);
                ldsm4(al, pa + i * 16 * PSTR * 4 + ks * 32 + ALO);
                mma16(acc[i][0], ah, bh0);     mma16(acc[i][0], ah, bl0);
                mma16(acc[i][0], al, bh0);
                mma16(acc[i][1], ah, bh0 + 2); mma16(acc[i][1], ah, bl0 + 2);
                mma16(acc[i][1], al, bh0 + 2);
                mma16(acc[i][2], ah, bh1);     mma16(acc[i][2], ah, bl1);
                mma16(acc[i][2], al, bh1);
                mma16(acc[i][3], ah, bh1 + 2); mma16(acc[i][3], ah, bl1 + 2);
                mma16(acc[i][3], al, bh1 + 2);
            }
        }
        __syncthreads();
    }

    // ---- epilogue: (+bias) * oscale; Q/K split bf16, V split FP16
#pragma unroll
    for (int j = 0; j < 4; j++) {
        const int col = n0 + wn + j * 8 + 2 * tig;
        const float bx = bias[col], by = bias[col + 1];
#pragma unroll
        for (int i = 0; i < 4; i++) {
            const int r0 = m0 + wm + i * 16 + g;
            uint32_t h0, l0, h1, l1;
            const float v0 = (acc[i][j][0] + bx) * oscale;
            const float v1 = (acc[i][j][1] + by) * oscale;
            const float v2 = (acc[i][j][2] + bx) * oscale;
            const float v3 = (acc[i][j][3] + by) * oscale;
            if (z == 2) {
                split2h(v0, v1, h0, l0);
                split2h(v2, v3, h1, l1);
            } else {
                split2(v0, v1, h0, l0);
                split2(v2, v3, h1, l1);
            }
            *(uint32_t*)&Yh[(size_t)r0 * DMODEL + col]       = h0;
            *(uint32_t*)&Yl[(size_t)r0 * DMODEL + col]       = l0;
            *(uint32_t*)&Yh[(size_t)(r0 + 8) * DMODEL + col] = h1;
            *(uint32_t*)&Yl[(size_t)(r0 + 8) * DMODEL + col] = l1;
        }
    }
}

// ---------------------------------------------------------------------------
// Flash attention over PACKED keys, double-buffered K/V.
// QK: bf16x3 (K pre-scaled into log2 domain). PV: 2-term FP16 (P single-fp16,
// V fp16 hi/lo) -> 64 MMAs/tile instead of 96.
// ---------------------------------------------------------------------------
#define ASTR   36
#define KVW    (4 * 64 * ASTR)
#define ATTN_SMEM ((2 * 128 * ASTR + 2 * KVW) * 4)   // 110592 bytes

__global__ __launch_bounds__(256, 2)
void attn_mma(float* __restrict__ out)
{
    extern __shared__ uint32_t smw[];
    const int tid  = threadIdx.x;
    const int lane = tid & 31;
    const int w    = tid >> 5;
    const int tig  = lane & 3;
    const int wm   = w * 16;
    const int q0   = blockIdx.x << 7;
    const int h    = blockIdx.y;
    const int b    = blockIdx.z;

    const size_t base = (size_t)b * SLEN * DMODEL + h * DHEAD;
    const __nv_bfloat16* qhg = g_qh + base;
    const __nv_bfloat16* qlg = g_ql + base;
    const __nv_bfloat16* khg = g_kh + base;
    const __nv_bfloat16* klg = g_kl + base;
    const __nv_bfloat16* vhg = g_vh + base;
    const __nv_bfloat16* vlg = g_vl + base;
    const int nvb   = g_nv[b];
    const int ntile = (nvb + 63) >> 6;

    const int lane15  = lane & 15;
    const int halfsel = (lane >> 4) & 1;
    const int krow    = (lane & 7) + ((lane & 16) >> 1);
    const int kcol    = (lane & 8) >> 1;

    const uint32_t sbase  = sptr(smw);
    const uint32_t kvbase = sbase + 9216u * 4;
    const uint32_t qa  = sbase + ((wm + lane15) * ASTR + halfsel * 4) * 4;
    const uint32_t QLO = 4608u * 4;
    const uint32_t kaB = (krow * ASTR + kcol) * 4;
    const uint32_t vaB = 4608u * 4 + (lane15 * ASTR + halfsel * 4) * 4;
    const uint32_t LO  = 2304u * 4;

    // ---- Q fill (cp.async)
#pragma unroll
    for (int it = 0; it < 4; it++) {
        const int idx = tid + it * 256;
        const int r = idx >> 3, ch = idx & 7;
        const size_t gg = (size_t)(q0 + r) * DMODEL + ch * 8;
        const uint32_t sm = (r * ASTR + ch * 4) * 4;
        cpa16(sbase + sm, qhg + gg);
        cpa16(sbase + QLO + sm, qlg + gg);
    }
    CP_COMMIT();

    // ---- K/V prefetch tile 0
#pragma unroll
    for (int it = 0; it < 2; it++) {
        const int idx = tid + it * 256;
        const int r = idx >> 3, ch = idx & 7;
        const size_t gg = (size_t)r * DMODEL + ch * 8;
        const uint32_t sm = (r * ASTR + ch * 4) * 4;
        cpa16(kvbase + sm,          khg + gg);
        cpa16(kvbase + LO + sm,     klg + gg);
        cpa16(kvbase + 2 * LO + sm, vhg + gg);
        cpa16(kvbase + 3 * LO + sm, vlg + gg);
    }
    CP_COMMIT();

    float O[8][4];
#pragma unroll
    for (int j = 0; j < 8; j++)
#pragma unroll
        for (int r = 0; r < 4; r++) O[j][r] = 0.f;
    float mrow0 = -1e30f, mrow1 = -1e30f, lrow0 = 0.f, lrow1 = 0.f;

    const unsigned FULL = 0xffffffffu;

    for (int t = 0; t < ntile; t++) {
        if (t + 1 < ntile) {
            const int k1 = (t + 1) << 6;
            const uint32_t st = kvbase + (uint32_t)((t + 1) & 1) * (KVW * 4);
#pragma unroll
            for (int it = 0; it < 2; it++) {
                const int idx = tid + it * 256;
                const int r = idx >> 3, ch = idx & 7;
                const size_t gg = (size_t)(k1 + r) * DMODEL + ch * 8;
                const uint32_t sm = (r * ASTR + ch * 4) * 4;
                cpa16(st + sm,          khg + gg);
                cpa16(st + LO + sm,     klg + gg);
                cpa16(st + 2 * LO + sm, vhg + gg);
                cpa16(st + 3 * LO + sm, vlg + gg);
            }
            CP_COMMIT();
            CP_WAIT(1);
        } else {
            CP_WAIT(0);
        }
        __syncthreads();

        const int k0 = t << 6;
        const uint32_t kvb = kvbase + (uint32_t)(t & 1) * (KVW * 4);
        const uint32_t ka = kvb + kaB;
        const uint32_t va = kvb + vaB;

        // ---- S = Q @ K^T (bf16x3; K pre-scaled into log2 domain)
        float S[8][4];
#pragma unroll
        for (int j = 0; j < 8; j++)
#pragma unroll
            for (int r = 0; r < 4; r++) S[j][r] = 0.f;

#pragma unroll
        for (int ks = 0; ks < 4; ks++) {
            uint32_t ah[4], al[4];
            ldsm4(ah, qa + ks * 32);
            ldsm4(al, qa + ks * 32 + QLO);
#pragma unroll
            for (int jp = 0; jp < 4; jp++) {
                uint32_t bh[4], bl[4];
                const uint32_t kaddr = ka + jp * 16 * ASTR * 4 + ks * 32;
                ldsm4(bh, kaddr);
                ldsm4(bl, kaddr + LO);
                mma16(S[2 * jp], ah, bh);         mma16(S[2 * jp], ah, bl);
                mma16(S[2 * jp], al, bh);
                mma16(S[2 * jp + 1], ah, bh + 2); mma16(S[2 * jp + 1], ah, bl + 2);
                mma16(S[2 * jp + 1], al, bh + 2);
            }
        }

        // ---- tail mask only on the final partial tile
        float mx0 = -1e30f, mx1 = -1e30f;
        if (k0 + 64 > nvb) {
#pragma unroll
            for (int j = 0; j < 8; j++) {
                const int c = k0 + j * 8 + 2 * tig;
                if (c >= nvb)     { S[j][0] = -1e9f; S[j][2] = -1e9f; }
                if (c + 1 >= nvb) { S[j][1] = -1e9f; S[j][3] = -1e9f; }
            }
        }
#pragma unroll
        for (int j = 0; j < 8; j++) {
            mx0 = fmaxf(mx0, fmaxf(S[j][0], S[j][1]));
            mx1 = fmaxf(mx1, fmaxf(S[j][2], S[j][3]));
        }
        mx0 = fmaxf(mx0, __shfl_xor_sync(FULL, mx0, 1));
        mx0 = fmaxf(mx0, __shfl_xor_sync(FULL, mx0, 2));
        mx1 = fmaxf(mx1, __shfl_xor_sync(FULL, mx1, 1));
        mx1 = fmaxf(mx1, __shfl_xor_sync(FULL, mx1, 2));

        const float mnew0 = fmaxf(mrow0, mx0);
        const float mnew1 = fmaxf(mrow1, mx1);
        const float fac0  = ex2(mrow0 - mnew0);
        const float fac1  = ex2(mrow1 - mnew1);

        float sum0 = 0.f, sum1 = 0.f;
#pragma unroll
        for (int j = 0; j < 8; j++) {
            S[j][0] = ex2(S[j][0] - mnew0);
            S[j][1] = ex2(S[j][1] - mnew0);
            S[j][2] = ex2(S[j][2] - mnew1);
            S[j][3] = ex2(S[j][3] - mnew1);
            sum0 += S[j][0] + S[j][1];
            sum1 += S[j][2] + S[j][3];
        }
        sum0 += __shfl_xor_sync(FULL, sum0, 1);
        sum0 += __shfl_xor_sync(FULL, sum0, 2);
        sum1 += __shfl_xor_sync(FULL, sum1, 1);
        sum1 += __shfl_xor_sync(FULL, sum1, 2);

        lrow0 = lrow0 * fac0 + sum0;
        lrow1 = lrow1 * fac1 + sum1;
        mrow0 = mnew0;
        mrow1 = mnew1;

#pragma unroll
        for (int j = 0; j < 8; j++) {
            O[j][0] *= fac0; O[j][1] *= fac0;
            O[j][2] *= fac1; O[j][3] *= fac1;
        }

        // ---- O += P @ V : P single-fp16 a-frag, V fp16 hi/lo (2 MMAs)
#pragma unroll
        for (int ks = 0; ks < 4; ks++) {
            uint32_t ap[4];
            ap[0] = packh2(S[2 * ks][0],     S[2 * ks][1]);
            ap[1] = packh2(S[2 * ks][2],     S[2 * ks][3]);
            ap[2] = packh2(S[2 * ks + 1][0], S[2 * ks + 1][1]);
            ap[3] = packh2(S[2 * ks + 1][2], S[2 * ks + 1][3]);
#pragma unroll
            for (int jnp = 0; jnp < 4; jnp++) {
                uint32_t bh[4], bl[4];
                const uint32_t vaddr = va + ks * 16 * ASTR * 4 + jnp * 32;
                ldsm4t(bh, vaddr);
                ldsm4t(bl, vaddr + LO);
                mma16h(O[2 * jnp], ap, bh);
                mma16h(O[2 * jnp], ap, bl);
                mma16h(O[2 * jnp + 1], ap, bh + 2);
                mma16h(O[2 * jnp + 1], ap, bl + 2);
            }
        }
        __syncthreads();
    }

    // ---- epilogue: normalize + store (float2)
    const int g2 = (lane >> 2);
    const float inv0 = 1.f / lrow0;
    const float inv1 = 1.f / lrow1;
    const int row0 = q0 + wm + g2;
#pragma unroll
    for (int jn = 0; jn < 8; jn++) {
        const int col = h * DHEAD + jn * 8 + 2 * tig;
        float2 v0, v1;
        v0.x = O[jn][0] * inv0; v0.y = O[jn][1] * inv0;
        v1.x = O[jn][2] * inv1; v1.y = O[jn][3] * inv1;
        *(float2*)(out + ((size_t)b * SLEN + row0) * DMODEL + col)     = v0;
        *(float2*)(out + ((size_t)b * SLEN + row0 + 8) * DMODEL + col) = v1;
    }
}

// ---------------------------------------------------------------------------
extern "C" void kernel_launch(void* const* d_in, const int* in_sizes, int n_in,
                              void* d_out, int out_size)
{
    const float* Q    = (const float*)d_in[0];
    const float* K    = (const float*)d_in[1];
    const float* V    = (const float*)d_in[2];
    const int*   mask = (const int*)d_in[3];
    const float* Wq   = (const float*)d_in[4];
    const float* bq   = (const float*)d_in[5];
    const float* Wk   = (const float*)d_in[6];
    const float* bk   = (const float*)d_in[7];
    const float* Wv   = (const float*)d_in[8];
    const float* bv   = (const float*)d_in[9];
    float* out = (float*)d_out;

    compact_mask<<<BATCH, 256>>>(mask);

    const dim3 tgrid(DMODEL / 32, DMODEL / 32, 3);
    wT_split<<<tgrid, dim3(32, 8)>>>(Wq, Wk, Wv);

    cudaFuncSetAttribute(proj_mma, cudaFuncAttributeMaxDynamicSharedMemorySize,
                         PROJ_SMEM);
    const dim3 pgrid(DMODEL / 128, (BATCH * SLEN) / 128, 3);
    proj_mma<<<pgrid, 256, PROJ_SMEM>>>(Q, K, V, bq, bk, bv);

    cudaFuncSetAttribute(attn_mma, cudaFuncAttributeMaxDynamicSharedMemorySize,
                         ATTN_SMEM);
    const dim3 agrid(SLEN / 128, NHEAD, BATCH);
    attn_mma<<<agrid, 256, ATTN_SMEM>>>(out);
}